// round 17
// baseline (speedup 1.0000x reference)
#include <cuda_runtime.h>
#include <cuda_bf16.h>
#include <cuda_fp16.h>
#include <cstdint>

#define S_LEN 2048
#define HID   4096
#define NH    32
#define NKV   8
#define HD    128
#define KVD   (NKV*HD)   /* 1024 */
#define QD    (NH*HD)    /* 4096 */
#define WROWS (QD+2*KVD) /* 6144 */
#define ATT_SCALE 0.08838834764831845f
#define LOG2E     1.4426950408889634f

// ---------------------------------------------------------------------------
// Scratch (device globals; no runtime allocation allowed)
// ---------------------------------------------------------------------------
// fp16 GEMM operands: A split (hi+lo), B hi-only (2-pass scheme)
__device__ __half g_hsH[S_LEN*HID], g_hsL[S_LEN*HID];
__device__ __half g_WH [WROWS*HID];            // wq|wk|wv stacked, hi only
__device__ __half g_WOH[HID*QD];               // wo hi only
__device__ __half g_AOH[S_LEN*QD], g_AOL[S_LEN*QD];
// split bf16 Q/K/V for HMMA flash (written by QKV epilogue, post-RoPE)
// Q is pre-scaled by ATT_SCALE*LOG2E (scores land in log2 domain).
__device__ __nv_bfloat16 g_QH[S_LEN*QD],  g_QL[S_LEN*QD];
__device__ __nv_bfloat16 g_KH[S_LEN*KVD], g_KL[S_LEN*KVD];
__device__ __nv_bfloat16 g_VH[S_LEN*KVD], g_VL[S_LEN*KVD];

// ---------------------------------------------------------------------------
// mma.sync helpers (sm_80-level, compiles for compute_103)
// ---------------------------------------------------------------------------
__device__ __forceinline__ uint32_t smem_u32(const void* p) {
    uint32_t a;
    asm("{ .reg .u64 t; cvta.to.shared.u64 t, %1; cvt.u32.u64 %0, t; }"
        : "=r"(a) : "l"(p));
    return a;
}

__device__ __forceinline__ void ldsm_x4(uint32_t* r, uint32_t addr) {
    asm volatile("ldmatrix.sync.aligned.m8n8.x4.shared.b16 {%0,%1,%2,%3}, [%4];"
        : "=r"(r[0]), "=r"(r[1]), "=r"(r[2]), "=r"(r[3]) : "r"(addr));
}

__device__ __forceinline__ void ldsm_x4_t(uint32_t* r, uint32_t addr) {
    asm volatile("ldmatrix.sync.aligned.m8n8.x4.trans.shared.b16 {%0,%1,%2,%3}, [%4];"
        : "=r"(r[0]), "=r"(r[1]), "=r"(r[2]), "=r"(r[3]) : "r"(addr));
}

// bf16 HMMA (flash)
__device__ __forceinline__ void mma16816(float* d, const uint32_t* a,
                                         const uint32_t* b) {
    asm volatile(
        "mma.sync.aligned.m16n8k16.row.col.f32.bf16.bf16.f32 "
        "{%0,%1,%2,%3},{%4,%5,%6,%7},{%8,%9},{%0,%1,%2,%3};"
        : "+f"(d[0]), "+f"(d[1]), "+f"(d[2]), "+f"(d[3])
        : "r"(a[0]), "r"(a[1]), "r"(a[2]), "r"(a[3]), "r"(b[0]), "r"(b[1]));
}

// fp16 HMMA (GEMMs)
__device__ __forceinline__ void mma16816h(float* d, const uint32_t* a,
                                          const uint32_t* b) {
    asm volatile(
        "mma.sync.aligned.m16n8k16.row.col.f32.f16.f16.f32 "
        "{%0,%1,%2,%3},{%4,%5,%6,%7},{%8,%9},{%0,%1,%2,%3};"
        : "+f"(d[0]), "+f"(d[1]), "+f"(d[2]), "+f"(d[3])
        : "r"(a[0]), "r"(a[1]), "r"(a[2]), "r"(a[3]), "r"(b[0]), "r"(b[1]));
}

__device__ __forceinline__ void cp16(uint32_t saddr, const void* g) {
    asm volatile("cp.async.cg.shared.global [%0], [%1], 16;"
        :: "r"(saddr), "l"(g) : "memory");
}

#define CP_COMMIT() asm volatile("cp.async.commit_group;" ::: "memory")
#define CP_WAIT(n)  asm volatile("cp.async.wait_group %0;" :: "n"(n) : "memory")

// bf16 packers
__device__ __forceinline__ uint32_t pack_bf(float lo, float hi) {
    uint32_t r;
    asm("cvt.rn.bf16x2.f32 %0, %1, %2;" : "=r"(r) : "f"(hi), "f"(lo));
    return r;
}
__device__ __forceinline__ uint32_t pack_hi2(float a, float b,
                                             float& ra, float& rb) {
    __nv_bfloat16 ha = __float2bfloat16(a), hb = __float2bfloat16(b);
    ra = a - __bfloat162float(ha);
    rb = b - __bfloat162float(hb);
    __nv_bfloat162 t{ha, hb};
    return *(uint32_t*)&t;
}

// fp16 packers
__device__ __forceinline__ uint32_t pack_h2(float a, float b) {
    __half2 t{__float2half_rn(a), __float2half_rn(b)};
    return *(uint32_t*)&t;
}
__device__ __forceinline__ uint32_t pack_hi2h(float a, float b,
                                              float& ra, float& rb) {
    __half ha = __float2half_rn(a), hb = __float2half_rn(b);
    ra = a - __half2float(ha);
    rb = b - __half2float(hb);
    __half2 t{ha, hb};
    return *(uint32_t*)&t;
}

// ---------------------------------------------------------------------------
// fp16 2-pass HMMA GEMM core (unchanged from R16 — structural plateau).
// ---------------------------------------------------------------------------
#define LDT       72
#define TILE_HB   (128*LDT*2)        /* 18432 B per 128x64 fp16 tile */
#define STAGE_B   (3*TILE_HB)        /* Ah, Al, Bh = 55296 B */
#define GEMM_SMEM (2*STAGE_B)        /* 110592 B */

__device__ __forceinline__ void mma_gemm_core(
    const __half* __restrict__ pAh, const __half* __restrict__ pAl,
    const __half* __restrict__ pBh,
    int K, float acc[4][4][4])
{
    extern __shared__ char smc[];
    const uint32_t smb = smem_u32(smc);
    const int tid = threadIdx.x;
    const int wid = tid >> 5;
    const int l   = tid & 31;
    const int wm  = wid & 1;
    const int wn  = wid >> 1;

    const int nk = K >> 6;

#define ISSUE_STAGE(s, kb) do {                                              \
        uint32_t sb_ = smb + (s) * STAGE_B;                                  \
        _Pragma("unroll")                                                    \
        for (int t = 0; t < 12; t++) {                                       \
            const int tile = t >> 2;                                         \
            int c_ = tid + (t & 3) * 256;                                    \
            const __half* src =                                              \
                (tile == 0) ? pAh : (tile == 1) ? pAl : pBh;                 \
            int row = c_ >> 3;                                               \
            int ch  = c_ & 7;                                                \
            cp16(sb_ + tile * TILE_HB + (row * LDT + ch * 8) * 2,            \
                 src + (size_t)row * K + (kb) + ch * 8);                     \
        }                                                                    \
        CP_COMMIT();                                                         \
    } while (0)

    ISSUE_STAGE(0, 0);

    for (int kt = 0; kt < nk; kt++) {
        const int s = kt & 1;
        if (kt + 1 < nk) {
            ISSUE_STAGE(s ^ 1, (kt + 1) << 6);
            CP_WAIT(1);
        } else {
            CP_WAIT(0);
        }
        __syncthreads();

        const uint32_t aAh = smb + s * STAGE_B;
        const uint32_t aAl = aAh + TILE_HB;
        const uint32_t aBh = aAh + 2 * TILE_HB;

#pragma unroll
        for (int ks = 0; ks < 4; ks++) {
            const int k0 = ks * 16;
            uint32_t ah[4][4], al[4][4], bh[2][4];
#pragma unroll
            for (int p = 0; p < 2; p++) {
                uint32_t off = (uint32_t)((wn * 16 + p * 64 + 8 * (l >> 4) + (l & 7)) * LDT
                                          + k0 + 8 * ((l >> 3) & 1)) * 2;
                ldsm_x4(bh[p], aBh + off);
            }
#pragma unroll
            for (int mt = 0; mt < 4; mt++) {
                uint32_t off = (uint32_t)((wm * 64 + mt * 16 + (l & 15)) * LDT
                                          + k0 + 8 * (l >> 4)) * 2;
                ldsm_x4(ah[mt], aAh + off);
                ldsm_x4(al[mt], aAl + off);
            }
#pragma unroll
            for (int mt = 0; mt < 4; mt++)
#pragma unroll
                for (int nt = 0; nt < 4; nt++)
                    mma16816h(acc[mt][nt], ah[mt], &bh[nt >> 1][(nt & 1) * 2]);
#pragma unroll
            for (int mt = 0; mt < 4; mt++)
#pragma unroll
                for (int nt = 0; nt < 4; nt++)
                    mma16816h(acc[mt][nt], al[mt], &bh[nt >> 1][(nt & 1) * 2]);
        }
        __syncthreads();
    }
#undef ISSUE_STAGE
}

// Epilogue fuses RoPE (Q,K) / plain split (V); Q pre-scaled by
// ATT_SCALE*LOG2E (flash softmax runs in exp2 domain).
__global__ void __launch_bounds__(256, 2) qkv_mma_kernel(
    const float* __restrict__ cosb, const float* __restrict__ sinb)
{
    const int m0 = blockIdx.x * 128;
    const int by = blockIdx.y;
    size_t wrow; int ldc; __nv_bfloat16 *dH, *dL; size_t n0;
    bool isV = false;
    float oscale = 1.0f;
    if (by < 32)      { ldc = QD;  n0 = (size_t)by << 7;        wrow = (size_t)(by << 7);
                        dH = g_QH; dL = g_QL; oscale = ATT_SCALE * LOG2E; }
    else if (by < 40) { ldc = KVD; n0 = (size_t)(by - 32) << 7; wrow = (size_t)QD + ((by - 32) << 7);
                        dH = g_KH; dL = g_KL; }
    else              { ldc = KVD; n0 = (size_t)(by - 40) << 7; wrow = (size_t)(QD + KVD) + ((by - 40) << 7);
                        dH = g_VH; dL = g_VL; isV = true; }

    float acc[4][4][4] = {};
    mma_gemm_core(g_hsH + (size_t)m0 * HID, g_hsL + (size_t)m0 * HID,
                  g_WH + wrow * HID, HID, acc);

    const int tid = threadIdx.x;
    const int wid = tid >> 5;
    const int l   = tid & 31;
    const int wm  = wid & 1;
    const int wn  = wid >> 1;
    const int m_base = m0 + wm * 64;

#pragma unroll
    for (int mt = 0; mt < 4; mt++)
#pragma unroll
        for (int rr = 0; rr < 2; rr++) {
            const int s = m_base + mt * 16 + (l >> 2) + rr * 8;
#pragma unroll
            for (int nt = 0; nt < 2; nt++) {
                const int d = wn * 16 + nt * 8 + 2 * (l & 3);
                float x1a = acc[mt][nt][rr * 2],     x1b = acc[mt][nt][rr * 2 + 1];
                float x2a = acc[mt][nt + 2][rr * 2], x2b = acc[mt][nt + 2][rr * 2 + 1];
                float r1a, r1b, r2a, r2b;
                if (!isV) {
                    float2 c2 = *(const float2*)(cosb + s * HD + d);
                    float2 s2 = *(const float2*)(sinb + s * HD + d);
                    r1a = (x1a * c2.x - x2a * s2.x) * oscale;
                    r1b = (x1b * c2.y - x2b * s2.y) * oscale;
                    r2a = (x2a * c2.x + x1a * s2.x) * oscale;
                    r2b = (x2b * c2.y + x1b * s2.y) * oscale;
                } else {
                    r1a = x1a; r1b = x1b; r2a = x2a; r2b = x2b;
                }
                float ra, rb;
                uint32_t h1 = pack_hi2(r1a, r1b, ra, rb);
                uint32_t l1 = pack_bf(ra, rb);
                uint32_t h2 = pack_hi2(r2a, r2b, ra, rb);
                uint32_t l2 = pack_bf(ra, rb);
                size_t o = (size_t)s * ldc + n0 + d;
                *(uint32_t*)(dH + o)      = h1;
                *(uint32_t*)(dL + o)      = l1;
                *(uint32_t*)(dH + o + 64) = h2;
                *(uint32_t*)(dL + o + 64) = l2;
            }
        }
}

__global__ void __launch_bounds__(256, 2) o_mma_kernel(float* __restrict__ out)
{
    const int m0 = blockIdx.x * 128;
    const int n0 = blockIdx.y * 128;
    float acc[4][4][4] = {};
    mma_gemm_core(g_AOH + (size_t)m0 * QD, g_AOL + (size_t)m0 * QD,
                  g_WOH + (size_t)n0 * QD, QD, acc);

    const int tid = threadIdx.x;
    const int wid = tid >> 5;
    const int l   = tid & 31;
    const int wm  = wid & 1;
    const int wn  = wid >> 1;
    const int m_base = m0 + wm * 64;

#pragma unroll
    for (int mt = 0; mt < 4; mt++)
#pragma unroll
        for (int nt = 0; nt < 4; nt++) {
            int col = n0 + wn * 16 + ((nt >> 1) << 6) + (nt & 1) * 8 + 2 * (l & 3);
            int row = m_base + mt * 16 + (l >> 2);
            float2 v0 = {acc[mt][nt][0], acc[mt][nt][1]};
            float2 v1 = {acc[mt][nt][2], acc[mt][nt][3]};
            *(float2*)(out + (size_t)row * HID + col)       = v0;
            *(float2*)(out + (size_t)(row + 8) * HID + col) = v1;
        }
}

// ---------------------------------------------------------------------------
// fp32 -> fp16 conversions, 16 elems/thread (MLP=4), 16B stores.
// ---------------------------------------------------------------------------
__device__ __forceinline__ void cvt16h(const float* __restrict__ src,
                                       __half* __restrict__ hi,
                                       __half* __restrict__ lo, int i)
{
    float4 v[4];
    v[0] = *(const float4*)(src + i);
    v[1] = *(const float4*)(src + i + 4);
    v[2] = *(const float4*)(src + i + 8);
    v[3] = *(const float4*)(src + i + 12);
    const float* x = (const float*)v;
    uint32_t hw[8], lw[8];
#pragma unroll
    for (int j = 0; j < 8; j++) {
        float r0, r1;
        hw[j] = pack_hi2h(x[2 * j], x[2 * j + 1], r0, r1);
        lw[j] = pack_h2(r0, r1);
    }
    *(uint4*)(hi + i)     = *(uint4*)hw;
    *(uint4*)(hi + i + 8) = *(uint4*)(hw + 4);
    *(uint4*)(lo + i)     = *(uint4*)lw;
    *(uint4*)(lo + i + 8) = *(uint4*)(lw + 4);
}

__device__ __forceinline__ void cvt16h_hi(const float* __restrict__ src,
                                          __half* __restrict__ hi, int i)
{
    float4 v[4];
    v[0] = *(const float4*)(src + i);
    v[1] = *(const float4*)(src + i + 4);
    v[2] = *(const float4*)(src + i + 8);
    v[3] = *(const float4*)(src + i + 12);
    const float* x = (const float*)v;
    uint32_t hw[8];
#pragma unroll
    for (int j = 0; j < 8; j++) hw[j] = pack_h2(x[2 * j], x[2 * j + 1]);
    *(uint4*)(hi + i)     = *(uint4*)hw;
    *(uint4*)(hi + i + 8) = *(uint4*)(hw + 4);
}

__global__ void cvt_all_kernel(const float* __restrict__ hs,
                               const float* __restrict__ wq,
                               const float* __restrict__ wk,
                               const float* __restrict__ wv,
                               const float* __restrict__ wo)
{
    const int NH16  = S_LEN * HID / 16;
    const int NWQ16 = QD * HID / 16;
    const int NWK16 = KVD * HID / 16;
    int u = blockIdx.x * blockDim.x + threadIdx.x;
    if (u < NH16) { cvt16h(hs, g_hsH, g_hsL, u << 4); return; }
    u -= NH16;
    if (u < NWQ16) { cvt16h_hi(wq, g_WH, u << 4); return; }
    u -= NWQ16;
    if (u < NWK16) { cvt16h_hi(wk, g_WH + (size_t)QD * HID, u << 4); return; }
    u -= NWK16;
    if (u < NWK16) { cvt16h_hi(wv, g_WH + (size_t)(QD + KVD) * HID, u << 4); return; }
    u -= NWK16;
    if (u < NWQ16) cvt16h_hi(wo, g_WOH, u << 4);
}
#define CVT_ALL_BLOCKS ((S_LEN*HID/16 + 2*(QD*HID/16) + 2*(KVD*HID/16)) / 256)

// ---------------------------------------------------------------------------
// HMMA causal flash attention (split-bf16, 3-pass). Scores in exp2 domain
// (Q pre-scaled by ATT_SCALE*LOG2E). exp2 of each column chunk interleaved
// into its PV iteration so MUFU hides under tensor ops.
// ---------------------------------------------------------------------------
#define LDF 136
#define FTILE (64*LDF*2)            /* 17408 B */
#define FLASH_SMEM (6*FTILE)        /* 104448 B -> 2 CTAs/SM */

__global__ void __launch_bounds__(128) flash_mma_kernel()
{
    extern __shared__ char fsm[];
    const uint32_t smb = smem_u32(fsm);
    const int tid = threadIdx.x;
    const int w   = tid >> 5;
    const int l   = tid & 31;
    const int qt  = 31 - (int)blockIdx.x;
    const int h   = blockIdx.y;
    const int kvh = h >> 2;

    const uint32_t sQH = smb;
    const uint32_t sQL = smb + FTILE;
    const uint32_t sKH = smb + 2 * FTILE;
    const uint32_t sKL = smb + 3 * FTILE;
    const uint32_t sVH = smb + 4 * FTILE;
    const uint32_t sVL = smb + 5 * FTILE;

#define LOAD_K(jt_) do {                                                     \
        const size_t kb_ = (size_t)((jt_) * 64) * KVD + kvh * HD;            \
        _Pragma("unroll")                                                    \
        for (int t = 0; t < 8; t++) {                                        \
            int idx = tid + t * 128;                                         \
            int row = idx >> 4, c8 = (idx & 15) << 3;                        \
            uint32_t doff = (uint32_t)(row * LDF + c8) * 2;                  \
            size_t gs = kb_ + (size_t)row * KVD + c8;                        \
            cp16(sKH + doff, g_KH + gs);                                     \
            cp16(sKL + doff, g_KL + gs);                                     \
        }                                                                    \
        CP_COMMIT();                                                         \
    } while (0)

#define LOAD_V(jt_) do {                                                     \
        const size_t kb_ = (size_t)((jt_) * 64) * KVD + kvh * HD;            \
        _Pragma("unroll")                                                    \
        for (int t = 0; t < 8; t++) {                                        \
            int idx = tid + t * 128;                                         \
            int row = idx >> 4, c8 = (idx & 15) << 3;                        \
            uint32_t doff = (uint32_t)(row * LDF + c8) * 2;                  \
            size_t gs = kb_ + (size_t)row * KVD + c8;                        \
            cp16(sVH + doff, g_VH + gs);                                     \
            cp16(sVL + doff, g_VL + gs);                                     \
        }                                                                    \
        CP_COMMIT();                                                         \
    } while (0)

    {
        const size_t qbase = (size_t)(qt * 64) * QD + h * HD;
#pragma unroll
        for (int t = 0; t < 8; t++) {
            int idx = tid + t * 128;
            int row = idx >> 4, c8 = (idx & 15) << 3;
            uint32_t doff = (uint32_t)(row * LDF + c8) * 2;
            cp16(sQH + doff, g_QH + qbase + (size_t)row * QD + c8);
            cp16(sQL + doff, g_QL + qbase + (size_t)row * QD + c8);
        }
        CP_COMMIT();
    }
    LOAD_K(0);
    LOAD_V(0);

    float S[8][4];
    float O[16][4] = {};
    float m0 = -1e30f, m1 = -1e30f, lr0 = 0.f, lr1 = 0.f;
    const int row0 = qt * 64 + w * 16 + (l >> 2);

    for (int jt = 0; jt <= qt; jt++) {
        CP_WAIT(1);
        __syncthreads();

        // ---- S = Q K^T (3-pass split; Q pre-scaled, log2 domain) ----
#pragma unroll
        for (int nt = 0; nt < 8; nt++) {
            S[nt][0] = S[nt][1] = S[nt][2] = S[nt][3] = 0.f;
        }
#pragma unroll
        for (int ks = 0; ks < 8; ks++) {
            uint32_t ah[4], al2[4], bh[4][4], bl[4][4];
            uint32_t aoff = (uint32_t)((w * 16 + (l & 15)) * LDF
                                       + ks * 16 + 8 * (l >> 4)) * 2;
            ldsm_x4(ah,  sQH + aoff);
            ldsm_x4(al2, sQL + aoff);
#pragma unroll
            for (int p = 0; p < 4; p++) {
                uint32_t boff = (uint32_t)((p * 16 + 8 * (l >> 4) + (l & 7)) * LDF
                                           + ks * 16 + 8 * ((l >> 3) & 1)) * 2;
                ldsm_x4(bh[p], sKH + boff);
                ldsm_x4(bl[p], sKL + boff);
            }
#pragma unroll
            for (int nt = 0; nt < 8; nt++) {
                const uint32_t* Bh_ = &bh[nt >> 1][(nt & 1) * 2];
                const uint32_t* Bl_ = &bl[nt >> 1][(nt & 1) * 2];
                mma16816(S[nt], ah,  Bh_);
                mma16816(S[nt], ah,  Bl_);
                mma16816(S[nt], al2, Bh_);
            }
        }
        __syncthreads();
        if (jt < qt) LOAD_K(jt + 1);

        // ---- causal mask ----
        const bool diag = (jt == qt);
        if (diag) {
#pragma unroll
            for (int nt = 0; nt < 8; nt++)
#pragma unroll
                for (int j = 0; j < 4; j++) {
                    int c = jt * 64 + nt * 8 + 2 * (l & 3) + (j & 1);
                    int r = row0 + (j >> 1) * 8;
                    if (c > r) S[nt][j] = -1e30f;
                }
        }

        // ---- max reduction + alpha + O rescale (exp chunks deferred) ----
        float mx0 = -1e30f, mx1 = -1e30f;
#pragma unroll
        for (int nt = 0; nt < 8; nt++) {
            mx0 = fmaxf(mx0, fmaxf(S[nt][0], S[nt][1]));
            mx1 = fmaxf(mx1, fmaxf(S[nt][2], S[nt][3]));
        }
        mx0 = fmaxf(mx0, __shfl_xor_sync(0xffffffffu, mx0, 1));
        mx0 = fmaxf(mx0, __shfl_xor_sync(0xffffffffu, mx0, 2));
        mx1 = fmaxf(mx1, __shfl_xor_sync(0xffffffffu, mx1, 1));
        mx1 = fmaxf(mx1, __shfl_xor_sync(0xffffffffu, mx1, 2));
        float mn0 = fmaxf(m0, mx0), mn1 = fmaxf(m1, mx1);
        float a0 = exp2f(m0 - mn0), a1 = exp2f(m1 - mn1);
        m0 = mn0; m1 = mn1;
#pragma unroll
        for (int nt = 0; nt < 16; nt++) {
            O[nt][0] *= a0; O[nt][1] *= a0;
            O[nt][2] *= a1; O[nt][3] *= a1;
        }
        float s0 = 0.f, s1 = 0.f;

        if (jt < qt) { CP_WAIT(1); } else { CP_WAIT(0); }
        __syncthreads();

        // ---- O += P V: exp2 of each column chunk interleaved with its PV ----
#pragma unroll
        for (int kk = 0; kk < 4; kk++) {
            uint32_t ph[4], pl[4];
            {
                float e00 = exp2f(S[2*kk][0]   - mn0);
                float e01 = exp2f(S[2*kk][1]   - mn0);
                float e02 = exp2f(S[2*kk][2]   - mn1);
                float e03 = exp2f(S[2*kk][3]   - mn1);
                float e10 = exp2f(S[2*kk+1][0] - mn0);
                float e11 = exp2f(S[2*kk+1][1] - mn0);
                float e12 = exp2f(S[2*kk+1][2] - mn1);
                float e13 = exp2f(S[2*kk+1][3] - mn1);
                s0 += e00 + e01; s1 += e02 + e03;
                s0 += e10 + e11; s1 += e12 + e13;
                float ra, rb;
                ph[0] = pack_hi2(e00, e01, ra, rb); pl[0] = pack_bf(ra, rb);
                ph[1] = pack_hi2(e02, e03, ra, rb); pl[1] = pack_bf(ra, rb);
                ph[2] = pack_hi2(e10, e11, ra, rb); pl[2] = pack_bf(ra, rb);
                ph[3] = pack_hi2(e12, e13, ra, rb); pl[3] = pack_bf(ra, rb);
            }
#pragma unroll
            for (int g = 0; g < 8; g++) {
                uint32_t vh[4], vl[4];
                uint32_t voff = (uint32_t)((kk * 16 + (l & 15)) * LDF
                                           + g * 16 + 8 * (l >> 4)) * 2;
                ldsm_x4_t(vh, sVH + voff);
                ldsm_x4_t(vl, sVL + voff);
                mma16816(O[2 * g],     ph, &vh[0]);
                mma16816(O[2 * g],     ph, &vl[0]);
                mma16816(O[2 * g],     pl, &vh[0]);
                mma16816(O[2 * g + 1], ph, &vh[2]);
                mma16816(O[2 * g + 1], ph, &vl[2]);
                mma16816(O[2 * g + 1], pl, &vh[2]);
            }
        }
        // row-sum reduction after the PV loop
        s0 += __shfl_xor_sync(0xffffffffu, s0, 1);
        s0 += __shfl_xor_sync(0xffffffffu, s0, 2);
        s1 += __shfl_xor_sync(0xffffffffu, s1, 1);
        s1 += __shfl_xor_sync(0xffffffffu, s1, 2);
        lr0 = lr0 * a0 + s0;
        lr1 = lr1 * a1 + s1;

        __syncthreads();
        if (jt < qt) LOAD_V(jt + 1);
    }

    // ---- normalize + write fp16 hi/lo AO (for fp16 O GEMM) ----
    float inv0 = 1.f / lr0, inv1 = 1.f / lr1;
    const size_t obase = (size_t)row0 * QD + h * HD;
#pragma unroll
    for (int nt = 0; nt < 16; nt++) {
        int col = nt * 8 + 2 * (l & 3);
        float ra, rb;
        uint32_t hv0 = pack_hi2h(O[nt][0] * inv0, O[nt][1] * inv0, ra, rb);
        uint32_t lv0 = pack_h2(ra, rb);
        uint32_t hv1 = pack_hi2h(O[nt][2] * inv1, O[nt][3] * inv1, ra, rb);
        uint32_t lv1 = pack_h2(ra, rb);
        *(uint32_t*)(g_AOH + obase + col)          = hv0;
        *(uint32_t*)(g_AOL + obase + col)          = lv0;
        *(uint32_t*)(g_AOH + obase + 8 * QD + col) = hv1;
        *(uint32_t*)(g_AOL + obase + 8 * QD + col) = lv1;
    }
#undef LOAD_K
#undef LOAD_V
}

// ---------------------------------------------------------------------------
// Launch
// ---------------------------------------------------------------------------
extern "C" void kernel_launch(void* const* d_in, const int* in_sizes, int n_in,
                              void* d_out, int out_size)
{
    const float* hs   = (const float*)d_in[0];
    const float* cosb = (const float*)d_in[1];
    const float* sinb = (const float*)d_in[2];
    const float* wq   = (const float*)d_in[3];
    const float* wk   = (const float*)d_in[4];
    const float* wv   = (const float*)d_in[5];
    const float* wo   = (const float*)d_in[6];
    // d_in[7..9] (k_cache, v_cache, block_ids): scatter/gather is an identity.
    float* out = (float*)d_out;

    cudaFuncSetAttribute(qkv_mma_kernel,
                         cudaFuncAttributeMaxDynamicSharedMemorySize, GEMM_SMEM);
    cudaFuncSetAttribute(o_mma_kernel,
                         cudaFuncAttributeMaxDynamicSharedMemorySize, GEMM_SMEM);
    cudaFuncSetAttribute(flash_mma_kernel,
                         cudaFuncAttributeMaxDynamicSharedMemorySize, FLASH_SMEM);

    // 1) fp32 -> fp16 conversions (hs split, weights hi-only)
    cvt_all_kernel<<<CVT_ALL_BLOCKS, 256>>>(hs, wq, wk, wv, wo);

    // 2) QKV projections with fused RoPE + (ATT_SCALE*LOG2E on Q) epilogue
    qkv_mma_kernel<<<dim3(16, 48), 256, GEMM_SMEM>>>(cosb, sinb);

    // 3) HMMA causal flash attention (exp2 domain, MUFU/tensor interleaved)
    flash_mma_kernel<<<dim3(32, 32), 128, FLASH_SMEM>>>();

    // 4) O projection
    o_mma_kernel<<<dim3(16, 32), 256, GEMM_SMEM>>>(out);
}